// round 1
// baseline (speedup 1.0000x reference)
#include <cuda_runtime.h>
#include <math.h>

// GRU: B=32, S=2048, H=512, 2 layers. fp32 throughout.
#define H   512
#define Bz  32
#define Sz  2048
#define G3  1536

// ---------------- static device scratch (no allocations allowed) -------------
__device__ float g_ip[(size_t)Sz * Bz * G3];   // input-projection buffer (reused by both layers)
__device__ float g_y0[(size_t)Sz * Bz * H];    // layer0 output, stored [s][b][h]
__device__ float g_h[2][Bz * H];               // double-buffered hidden state
__device__ unsigned long long g_cnt = 0;       // barrier arrivals (monotonic across replays)
__device__ unsigned long long g_gen = 0;       // barrier generation

// ---------------- persistent scan kernel config ------------------------------
#define NBLK 128          // <= 148 SMs, 1 block/SM (smem-limited) -> co-resident, barrier safe
#define NTHR 512
#define JT   16           // j's per block  (512 / 32 j-tiles)
#define BT   8            // batches per block (32 / 4 b-tiles)
#define ROWS 48           // 3 gates * JT
#define SMEM_FLOATS (ROWS*H + BT*H + ROWS*BT)
#define SMEM_BYTES  (SMEM_FLOATS * 4)

__device__ __forceinline__ void grid_barrier()
{
    __syncthreads();
    if (threadIdx.x == 0) {
        __threadfence();
        unsigned long long old = atomicAdd(&g_cnt, 1ULL);
        unsigned long long epoch = old / (unsigned long long)NBLK;
        if ((old % NBLK) == NBLK - 1) {
            atomicAdd(&g_gen, 1ULL);           // release
        } else {
            while (*((volatile unsigned long long*)&g_gen) <= epoch) { }
        }
        __threadfence();
    }
    __syncthreads();
}

// One launch runs one full GRU layer scan (2048 steps) with grid barriers.
__global__ __launch_bounds__(NTHR, 1)
void gru_scan_kernel(const float* __restrict__ ip,   // [S][B][3H] (bi already added)
                     const float* __restrict__ Wh,   // [3H][H]
                     const float* __restrict__ bh,   // [3H]
                     float* __restrict__ y,          // layer0: [s][b][h]; layer1: [b][s][h]
                     float* __restrict__ hout,       // last hidden (layer1 only)
                     int last_layer)
{
    extern __shared__ float sm[];
    float* Wh_s = sm;                       // [ROWS][H]
    float* h_s  = sm + ROWS * H;            // [BT][H]
    float* hp_s = sm + ROWS * H + BT * H;   // [ROWS][BT]

    const int tid = threadIdx.x;
    const int bid = blockIdx.x;
    const int jt  = bid >> 2;               // 0..31
    const int bt  = bid & 3;                // 0..3
    const int j0  = jt * JT;
    const int b0  = bt * BT;

    // ---- load this block's Wh rows {j0..j0+15, H+j0.., 2H+j0..} once --------
    for (int f = tid; f < ROWS * (H / 4); f += NTHR) {
        int r    = f / (H / 4);
        int kc   = f % (H / 4);
        int gate = r / JT;
        int jl   = r % JT;
        int grow = gate * H + j0 + jl;
        ((float4*)Wh_s)[r * (H / 4) + kc] =
            ((const float4*)Wh)[(size_t)grow * (H / 4) + kc];
    }

    const int w    = tid >> 5;
    const int lane = tid & 31;
    const int rg   = (w & 7) * 6;    // 6 rows per warp  (8 row-groups)
    const int bg   = (w >> 3) * 4;   // 4 local batches  (2 batch-groups)

    // ---- gate-phase constants (threads 0..127 own one (j,b) output each) ----
    float bhr = 0.f, bhz = 0.f, bhn = 0.f;
    int g_jl = 0, g_bb = 0, bglob = 0;
    const bool gthread = (tid < JT * BT);
    if (gthread) {
        g_jl  = tid >> 3;
        g_bb  = tid & 7;
        bglob = b0 + g_bb;
        int j = j0 + g_jl;
        bhr = bh[j]; bhz = bh[H + j]; bhn = bh[2 * H + j];
    }

    for (int t = 0; t < Sz; t++) {
        // ---- stage current hidden slice (8 batches x 512) into smem ---------
        {
            const float4* hsrc = (const float4*)(&g_h[t & 1][b0 * H]);
            float4* hdst = (float4*)h_s;
            #pragma unroll
            for (int i = 0; i < (BT * H / 4) / NTHR; i++) {   // 2 iters
                int idx = tid + i * NTHR;
                float4 v;
                if (t == 0) v = make_float4(0.f, 0.f, 0.f, 0.f);
                else        v = __ldcg(hsrc + idx);            // bypass stale L1
                hdst[idx] = v;
            }
        }
        // ---- prefetch this step's ip values (hide DRAM latency under FMAs) --
        float ipr = 0.f, ipz = 0.f, ipn = 0.f;
        if (gthread) {
            const float* p = ip + ((size_t)t * Bz + bglob) * G3 + (j0 + g_jl);
            ipr = __ldg(p);
            ipz = __ldg(p + H);
            ipn = __ldg(p + 2 * H);
        }
        __syncthreads();

        // ---- hp = Wh_tile @ h  (warp: 6 rows x 4 batches, lanes split K) ----
        float acc[6][4];
        #pragma unroll
        for (int r = 0; r < 6; r++)
            #pragma unroll
            for (int b = 0; b < 4; b++) acc[r][b] = 0.f;

        #pragma unroll
        for (int i = 0; i < H / 32; i++) {
            int k = lane + 32 * i;
            float hv[4], wv[6];
            #pragma unroll
            for (int b = 0; b < 4; b++) hv[b] = h_s[(bg + b) * H + k];
            #pragma unroll
            for (int r = 0; r < 6; r++) wv[r] = Wh_s[(rg + r) * H + k];
            #pragma unroll
            for (int r = 0; r < 6; r++)
                #pragma unroll
                for (int b = 0; b < 4; b++)
                    acc[r][b] = fmaf(wv[r], hv[b], acc[r][b]);
        }
        #pragma unroll
        for (int r = 0; r < 6; r++)
            #pragma unroll
            for (int b = 0; b < 4; b++) {
                float v = acc[r][b];
                v += __shfl_xor_sync(0xffffffffu, v, 16);
                v += __shfl_xor_sync(0xffffffffu, v, 8);
                v += __shfl_xor_sync(0xffffffffu, v, 4);
                v += __shfl_xor_sync(0xffffffffu, v, 2);
                v += __shfl_xor_sync(0xffffffffu, v, 1);
                if (lane == 0) hp_s[(rg + r) * BT + (bg + b)] = v;
            }
        __syncthreads();

        // ---- gates + state update ------------------------------------------
        if (gthread) {
            float hpr = hp_s[g_jl * BT + g_bb] + bhr;
            float hpz = hp_s[(JT + g_jl) * BT + g_bb] + bhz;
            float hpn = hp_s[(2 * JT + g_jl) * BT + g_bb] + bhn;
            float hprev = h_s[g_bb * H + (j0 + g_jl)];
            float r = 1.f / (1.f + __expf(-(ipr + hpr)));
            float z = 1.f / (1.f + __expf(-(ipz + hpz)));
            float n = tanhf(ipn + r * hpn);
            float hy = (1.f - z) * n + z * hprev;
            int j = j0 + g_jl;
            __stcg(&g_h[(t + 1) & 1][bglob * H + j], hy);
            if (last_layer) {
                y[((size_t)bglob * Sz + t) * H + j] = hy;
                if (t == Sz - 1) hout[bglob * H + j] = hy;
            } else {
                y[((size_t)t * Bz + bglob) * H + j] = hy;
            }
            __threadfence();   // make hy visible before barrier release
        }
        if (t != Sz - 1) grid_barrier();
    }
}

// ---------------- fp32 input-projection GEMM ---------------------------------
// C[m][g] = sum_d A[row(m)][d] * W[g][d] + bias[g];  M=65536, N=1536, K=512
// row(m) offset = (m&31)*strideB + (m>>5)*strideS  (handles both x and y0 layouts)
#define GBM 128
#define GBN 128
#define GBK 8

__global__ __launch_bounds__(256, 1)
void gemm_wi_kernel(const float* __restrict__ A, const float* __restrict__ W,
                    const float* __restrict__ bias, float* __restrict__ C,
                    int strideB, int strideS)
{
    __shared__ __align__(16) float As[GBK][GBM];
    __shared__ __align__(16) float Bs[GBK][GBN];

    const int tid = threadIdx.x;
    const int m0 = blockIdx.y * GBM;
    const int n0 = blockIdx.x * GBN;
    const int ty = tid >> 4, tx = tid & 15;

    const int lrow = tid >> 1;            // 0..127
    const int lk   = (tid & 1) * 4;       // 0 or 4

    const int am = m0 + lrow;
    const size_t aoff = (size_t)(am & 31) * strideB + (size_t)(am >> 5) * strideS;
    const size_t boff = (size_t)(n0 + lrow) * H;

    float acc[8][8];
    #pragma unroll
    for (int i = 0; i < 8; i++)
        #pragma unroll
        for (int j = 0; j < 8; j++) acc[i][j] = 0.f;

    for (int k0 = 0; k0 < H; k0 += GBK) {
        float4 av = *(const float4*)(A + aoff + k0 + lk);
        float4 bv = *(const float4*)(W + boff + k0 + lk);
        As[lk + 0][lrow] = av.x; As[lk + 1][lrow] = av.y;
        As[lk + 2][lrow] = av.z; As[lk + 3][lrow] = av.w;
        Bs[lk + 0][lrow] = bv.x; Bs[lk + 1][lrow] = bv.y;
        Bs[lk + 2][lrow] = bv.z; Bs[lk + 3][lrow] = bv.w;
        __syncthreads();

        #pragma unroll
        for (int k = 0; k < GBK; k++) {
            float4 a0 = *(float4*)&As[k][ty * 8];
            float4 a1 = *(float4*)&As[k][ty * 8 + 4];
            float4 b0 = *(float4*)&Bs[k][tx * 8];
            float4 b1 = *(float4*)&Bs[k][tx * 8 + 4];
            float a[8] = {a0.x, a0.y, a0.z, a0.w, a1.x, a1.y, a1.z, a1.w};
            float b[8] = {b0.x, b0.y, b0.z, b0.w, b1.x, b1.y, b1.z, b1.w};
            #pragma unroll
            for (int i = 0; i < 8; i++)
                #pragma unroll
                for (int j = 0; j < 8; j++)
                    acc[i][j] = fmaf(a[i], b[j], acc[i][j]);
        }
        __syncthreads();
    }

    float bia[8];
    #pragma unroll
    for (int j = 0; j < 8; j++) bia[j] = bias[n0 + tx * 8 + j];

    #pragma unroll
    for (int i = 0; i < 8; i++) {
        int m = m0 + ty * 8 + i;
        float* crow = C + (size_t)m * G3 + n0 + tx * 8;
        float4 o0 = make_float4(acc[i][0] + bia[0], acc[i][1] + bia[1],
                                acc[i][2] + bia[2], acc[i][3] + bia[3]);
        float4 o1 = make_float4(acc[i][4] + bia[4], acc[i][5] + bia[5],
                                acc[i][6] + bia[6], acc[i][7] + bia[7]);
        *(float4*)(crow)     = o0;
        *(float4*)(crow + 4) = o1;
    }
}

// ---------------- launch ------------------------------------------------------
extern "C" void kernel_launch(void* const* d_in, const int* in_sizes, int n_in,
                              void* d_out, int out_size)
{
    const float* x   = (const float*)d_in[0];
    const float* Wi0 = (const float*)d_in[1];
    const float* bi0 = (const float*)d_in[2];
    const float* Wh0 = (const float*)d_in[3];
    const float* bh0 = (const float*)d_in[4];
    const float* Wi1 = (const float*)d_in[5];
    const float* bi1 = (const float*)d_in[6];
    const float* Wh1 = (const float*)d_in[7];
    const float* bh1 = (const float*)d_in[8];
    float* out = (float*)d_out;

    float *ip, *y0;
    cudaGetSymbolAddress((void**)&ip, g_ip);
    cudaGetSymbolAddress((void**)&y0, g_y0);

    cudaFuncSetAttribute(gru_scan_kernel,
                         cudaFuncAttributeMaxDynamicSharedMemorySize, SMEM_BYTES);

    dim3 gg(G3 / GBN, (Bz * Sz) / GBM);   // 12 x 512

    // layer 0: ip = x @ Wi0^T + bi0, then scan
    gemm_wi_kernel<<<gg, 256>>>(x, Wi0, bi0, ip, Sz * H, H);
    gru_scan_kernel<<<NBLK, NTHR, SMEM_BYTES>>>(ip, Wh0, bh0, y0, nullptr, 0);

    // layer 1: ip = y0 @ Wi1^T + bi1 (y0 is [s][b][h] -> row m contiguous), then scan
    gemm_wi_kernel<<<gg, 256>>>(y0, Wi1, bi1, ip, H, Bz * H);
    gru_scan_kernel<<<NBLK, NTHR, SMEM_BYTES>>>(ip, Wh1, bh1, out,
                                                out + (size_t)Bz * Sz * H, 1);

    (void)in_sizes; (void)n_in; (void)out_size;
}

// round 2
// speedup vs baseline: 1.0305x; 1.0305x over previous
#include <cuda_runtime.h>
#include <math.h>

// GRU: B=32, S=2048, H=512, 2 layers. fp32 throughout.
#define H   512
#define Bz  32
#define Sz  2048
#define G3  1536

// ---------------- static device scratch (no allocations allowed) -------------
__device__ float g_ip[(size_t)Sz * Bz * G3];   // input-projection buffer (reused by both layers)
__device__ float g_y0[(size_t)Sz * Bz * H];    // layer0 output, stored [s][b][h]
__device__ float g_h[2][Bz * H];               // double-buffered hidden state
// 4 independent group barriers (one per batch-group), padded to own cache lines
__device__ unsigned long long g_cnt4[4][16];
__device__ unsigned long long g_gen4[4][16];

// ---------------- persistent scan kernel config ------------------------------
#define NBLK 128          // <= 148 SMs, 1 block/SM (smem-limited) -> co-resident, barrier safe
#define NTHR 512
#define JT   16           // j's per block  (512 / 32 j-tiles)
#define BT   8            // batches per block (32 / 4 b-tiles)
#define ROWS 48           // 3 gates * JT
#define GRPBLK 32         // blocks per barrier group (same bt)
#define SMEM_FLOATS (ROWS*H + BT*H + ROWS*BT)
#define SMEM_BYTES  (SMEM_FLOATS * 4)

// Barrier over the 32 blocks sharing one batch-group. CG-style release/acquire:
// writers' stores -> __syncthreads -> t0 fence+release-add -> readers' acquire
// spin -> fence -> __syncthreads. Counters are monotonic across graph replays.
__device__ __forceinline__ void group_barrier(int grp)
{
    __syncthreads();
    if (threadIdx.x == 0) {
        __threadfence();
        unsigned long long old = atomicAdd(&g_cnt4[grp][0], 1ULL);
        unsigned long long epoch = old >> 5;            // /GRPBLK
        if ((old & (GRPBLK - 1)) == GRPBLK - 1) {
            atomicAdd(&g_gen4[grp][0], 1ULL);           // release
        } else {
            while (*((volatile unsigned long long*)&g_gen4[grp][0]) <= epoch) { }
        }
        __threadfence();
    }
    __syncthreads();
}

// One launch runs one full GRU layer scan (2048 steps) with group barriers.
__global__ __launch_bounds__(NTHR, 1)
void gru_scan_kernel(const float* __restrict__ ip,   // [S][B][3H] (bi already added)
                     const float* __restrict__ Wh,   // [3H][H]
                     const float* __restrict__ bh,   // [3H]
                     float* __restrict__ y,          // layer0: [s][b][h]; layer1: [b][s][h]
                     float* __restrict__ hout,       // last hidden (layer1 only)
                     int last_layer)
{
    extern __shared__ float sm[];
    float* Wh_s = sm;                       // [ROWS][H]
    float* h_s  = sm + ROWS * H;            // [BT][H]
    float* hp_s = sm + ROWS * H + BT * H;   // [ROWS][BT]

    const int tid = threadIdx.x;
    const int bid = blockIdx.x;
    const int jt  = bid >> 2;               // 0..31
    const int bt  = bid & 3;                // 0..3  (barrier group)
    const int j0  = jt * JT;
    const int b0  = bt * BT;

    // ---- load this block's Wh rows {j0..j0+15, H+j0.., 2H+j0..} once --------
    for (int f = tid; f < ROWS * (H / 4); f += NTHR) {
        int r    = f / (H / 4);
        int kc   = f % (H / 4);
        int gate = r / JT;
        int jl   = r % JT;
        int grow = gate * H + j0 + jl;
        ((float4*)Wh_s)[r * (H / 4) + kc] =
            ((const float4*)Wh)[(size_t)grow * (H / 4) + kc];
    }

    const int w    = tid >> 5;
    const int lane = tid & 31;
    const int rg   = (w & 7) * 6;    // 6 rows per warp  (8 row-groups)
    const int bg   = (w >> 3) * 4;   // 4 local batches  (2 batch-groups)

    // ---- gate-phase constants (threads 0..127 own one (j,b) output each) ----
    float bhr = 0.f, bhz = 0.f, bhn = 0.f;
    int g_jl = 0, g_bb = 0, bglob = 0;
    const float* ipp = ip;
    const bool gthread = (tid < JT * BT);
    if (gthread) {
        g_jl  = tid >> 3;
        g_bb  = tid & 7;
        bglob = b0 + g_bb;
        int j = j0 + g_jl;
        bhr = bh[j]; bhz = bh[H + j]; bhn = bh[2 * H + j];
        ipp = ip + (size_t)bglob * G3 + (j0 + g_jl);
    }

    // prefetch ip for t=0
    float ipr = 0.f, ipz = 0.f, ipn = 0.f;
    if (gthread) {
        ipr = __ldg(ipp);
        ipz = __ldg(ipp + H);
        ipn = __ldg(ipp + 2 * H);
    }

    const float4* Wh4 = (const float4*)Wh_s;
    const float4* h4  = (const float4*)h_s;

    for (int t = 0; t < Sz; t++) {
        // ---- stage current hidden slice (8 batches x 512) into smem ---------
        {
            const float4* hsrc = (const float4*)(&g_h[t & 1][b0 * H]);
            float4* hdst = (float4*)h_s;
            #pragma unroll
            for (int i = 0; i < (BT * H / 4) / NTHR; i++) {   // 2 iters
                int idx = tid + i * NTHR;
                float4 v;
                if (t == 0) v = make_float4(0.f, 0.f, 0.f, 0.f);
                else        v = __ldcg(hsrc + idx);            // bypass stale L1
                hdst[idx] = v;
            }
        }
        __syncthreads();

        // ---- hp = Wh_tile @ h  (warp: 6 rows x 4 batches, lanes split K4) ---
        float acc[6][4];
        #pragma unroll
        for (int r = 0; r < 6; r++)
            #pragma unroll
            for (int b = 0; b < 4; b++) acc[r][b] = 0.f;

        #pragma unroll
        for (int i = 0; i < H / 4 / 32; i++) {                 // 4 iters
            int k4 = lane + 32 * i;
            float4 hv[4], wv[6];
            #pragma unroll
            for (int b = 0; b < 4; b++) hv[b] = h4[(bg + b) * (H / 4) + k4];
            #pragma unroll
            for (int r = 0; r < 6; r++) wv[r] = Wh4[(rg + r) * (H / 4) + k4];
            #pragma unroll
            for (int r = 0; r < 6; r++)
                #pragma unroll
                for (int b = 0; b < 4; b++) {
                    acc[r][b] = fmaf(wv[r].x, hv[b].x, acc[r][b]);
                    acc[r][b] = fmaf(wv[r].y, hv[b].y, acc[r][b]);
                    acc[r][b] = fmaf(wv[r].z, hv[b].z, acc[r][b]);
                    acc[r][b] = fmaf(wv[r].w, hv[b].w, acc[r][b]);
                }
        }
        #pragma unroll
        for (int r = 0; r < 6; r++)
            #pragma unroll
            for (int b = 0; b < 4; b++) {
                float v = acc[r][b];
                v += __shfl_xor_sync(0xffffffffu, v, 16);
                v += __shfl_xor_sync(0xffffffffu, v, 8);
                v += __shfl_xor_sync(0xffffffffu, v, 4);
                v += __shfl_xor_sync(0xffffffffu, v, 2);
                v += __shfl_xor_sync(0xffffffffu, v, 1);
                if (lane == 0) hp_s[(rg + r) * BT + (bg + b)] = v;
            }
        __syncthreads();

        // ---- gates + state update ------------------------------------------
        if (gthread) {
            float hpr = hp_s[g_jl * BT + g_bb] + bhr;
            float hpz = hp_s[(JT + g_jl) * BT + g_bb] + bhz;
            float hpn = hp_s[(2 * JT + g_jl) * BT + g_bb] + bhn;
            float hprev = h_s[g_bb * H + (j0 + g_jl)];
            float r = 1.f / (1.f + __expf(-(ipr + hpr)));
            float z = 1.f / (1.f + __expf(-(ipz + hpz)));
            float n = tanhf(ipn + r * hpn);
            float hy = (1.f - z) * n + z * hprev;
            int j = j0 + g_jl;
            __stcg(&g_h[(t + 1) & 1][bglob * H + j], hy);
            if (last_layer) {
                y[((size_t)bglob * Sz + t) * H + j] = hy;
                if (t == Sz - 1) hout[bglob * H + j] = hy;
            } else {
                y[((size_t)t * Bz + bglob) * H + j] = hy;
            }
            // prefetch next step's ip before the barrier (hide DRAM latency)
            if (t != Sz - 1) {
                const float* p = ipp + (size_t)(t + 1) * (Bz * G3);
                ipr = __ldg(p);
                ipz = __ldg(p + H);
                ipn = __ldg(p + 2 * H);
            }
        }
        if (t != Sz - 1) group_barrier(bt);
    }
}

// ---------------- fp32 input-projection GEMM ---------------------------------
// C[m][g] = sum_d A[row(m)][d] * W[g][d] + bias[g];  M=65536, N=1536, K=512
// row(m) offset = (m&31)*strideB + (m>>5)*strideS  (handles both x and y0 layouts)
#define GBM 128
#define GBN 128
#define GBK 8

__global__ __launch_bounds__(256, 1)
void gemm_wi_kernel(const float* __restrict__ A, const float* __restrict__ W,
                    const float* __restrict__ bias, float* __restrict__ C,
                    int strideB, int strideS)
{
    __shared__ __align__(16) float As[GBK][GBM];
    __shared__ __align__(16) float Bs[GBK][GBN];

    const int tid = threadIdx.x;
    const int m0 = blockIdx.y * GBM;
    const int n0 = blockIdx.x * GBN;
    const int ty = tid >> 4, tx = tid & 15;

    const int lrow = tid >> 1;            // 0..127
    const int lk   = (tid & 1) * 4;       // 0 or 4

    const int am = m0 + lrow;
    const size_t aoff = (size_t)(am & 31) * strideB + (size_t)(am >> 5) * strideS;
    const size_t boff = (size_t)(n0 + lrow) * H;

    float acc[8][8];
    #pragma unroll
    for (int i = 0; i < 8; i++)
        #pragma unroll
        for (int j = 0; j < 8; j++) acc[i][j] = 0.f;

    for (int k0 = 0; k0 < H; k0 += GBK) {
        float4 av = *(const float4*)(A + aoff + k0 + lk);
        float4 bv = *(const float4*)(W + boff + k0 + lk);
        As[lk + 0][lrow] = av.x; As[lk + 1][lrow] = av.y;
        As[lk + 2][lrow] = av.z; As[lk + 3][lrow] = av.w;
        Bs[lk + 0][lrow] = bv.x; Bs[lk + 1][lrow] = bv.y;
        Bs[lk + 2][lrow] = bv.z; Bs[lk + 3][lrow] = bv.w;
        __syncthreads();

        #pragma unroll
        for (int k = 0; k < GBK; k++) {
            float4 a0 = *(float4*)&As[k][ty * 8];
            float4 a1 = *(float4*)&As[k][ty * 8 + 4];
            float4 b0 = *(float4*)&Bs[k][tx * 8];
            float4 b1 = *(float4*)&Bs[k][tx * 8 + 4];
            float a[8] = {a0.x, a0.y, a0.z, a0.w, a1.x, a1.y, a1.z, a1.w};
            float b[8] = {b0.x, b0.y, b0.z, b0.w, b1.x, b1.y, b1.z, b1.w};
            #pragma unroll
            for (int i = 0; i < 8; i++)
                #pragma unroll
                for (int j = 0; j < 8; j++)
                    acc[i][j] = fmaf(a[i], b[j], acc[i][j]);
        }
        __syncthreads();
    }

    float bia[8];
    #pragma unroll
    for (int j = 0; j < 8; j++) bia[j] = bias[n0 + tx * 8 + j];

    #pragma unroll
    for (int i = 0; i < 8; i++) {
        int m = m0 + ty * 8 + i;
        float* crow = C + (size_t)m * G3 + n0 + tx * 8;
        float4 o0 = make_float4(acc[i][0] + bia[0], acc[i][1] + bia[1],
                                acc[i][2] + bia[2], acc[i][3] + bia[3]);
        float4 o1 = make_float4(acc[i][4] + bia[4], acc[i][5] + bia[5],
                                acc[i][6] + bia[6], acc[i][7] + bia[7]);
        *(float4*)(crow)     = o0;
        *(float4*)(crow + 4) = o1;
    }
}

// ---------------- launch ------------------------------------------------------
extern "C" void kernel_launch(void* const* d_in, const int* in_sizes, int n_in,
                              void* d_out, int out_size)
{
    const float* x   = (const float*)d_in[0];
    const float* Wi0 = (const float*)d_in[1];
    const float* bi0 = (const float*)d_in[2];
    const float* Wh0 = (const float*)d_in[3];
    const float* bh0 = (const float*)d_in[4];
    const float* Wi1 = (const float*)d_in[5];
    const float* bi1 = (const float*)d_in[6];
    const float* Wh1 = (const float*)d_in[7];
    const float* bh1 = (const float*)d_in[8];
    float* out = (float*)d_out;

    float *ip, *y0;
    cudaGetSymbolAddress((void**)&ip, g_ip);
    cudaGetSymbolAddress((void**)&y0, g_y0);

    cudaFuncSetAttribute(gru_scan_kernel,
                         cudaFuncAttributeMaxDynamicSharedMemorySize, SMEM_BYTES);

    dim3 gg(G3 / GBN, (Bz * Sz) / GBM);   // 12 x 512

    // layer 0: ip = x @ Wi0^T + bi0, then scan
    gemm_wi_kernel<<<gg, 256>>>(x, Wi0, bi0, ip, Sz * H, H);
    gru_scan_kernel<<<NBLK, NTHR, SMEM_BYTES>>>(ip, Wh0, bh0, y0, nullptr, 0);

    // layer 1: ip = y0 @ Wi1^T + bi1 (y0 is [s][b][h] -> row m contiguous), then scan
    gemm_wi_kernel<<<gg, 256>>>(y0, Wi1, bi1, ip, H, Bz * H);
    gru_scan_kernel<<<NBLK, NTHR, SMEM_BYTES>>>(ip, Wh1, bh1, out,
                                                out + (size_t)Bz * Sz * H, 1);

    (void)in_sizes; (void)n_in; (void)out_size;
}

// round 6
// speedup vs baseline: 1.1601x; 1.1257x over previous
#include <cuda_runtime.h>
#include <math.h>

// GRU: B=32, S=2048, H=512, 2 layers. fp32 (f32x2-packed math).
#define H   512
#define Bz  32
#define Sz  2048
#define G3  1536

// ---------------- static device scratch (no allocations allowed) -------------
__device__ float g_ip[(size_t)Sz * Bz * G3];   // input-projection buffer
__device__ float g_y0[(size_t)Sz * Bz * H];    // layer0 output, [s][b][h]
__device__ float g_h[2][Bz * H];               // double-buffered hidden state
__device__ unsigned long long g_cnt4[4][16];   // per-group barrier arrivals
__device__ unsigned long long g_gen4[4][16];   // per-group barrier generation

// ---------------- packed f32x2 helpers (Blackwell) ---------------------------
#define FMA2(d, a, b, c) \
    asm("fma.rn.f32x2 %0, %1, %2, %3;" : "=l"(d) : "l"(a), "l"(b), "l"(c))

__device__ __forceinline__ unsigned long long pack2(float lo, float hi) {
    unsigned long long r;
    asm("mov.b64 %0, {%1, %2};" : "=l"(r) : "f"(lo), "f"(hi));
    return r;
}
__device__ __forceinline__ float2 unpack2(unsigned long long v) {
    float2 f;
    asm("mov.b64 {%0, %1}, %2;" : "=f"(f.x), "=f"(f.y) : "l"(v));
    return f;
}

// ---------------- release/acquire barrier primitives -------------------------
__device__ __forceinline__ unsigned long long atom_add_release(unsigned long long* p) {
    unsigned long long old;
    asm volatile("atom.release.gpu.global.add.u64 %0, [%1], 1;"
                 : "=l"(old) : "l"(p) : "memory");
    return old;
}
__device__ __forceinline__ void red_add_release(unsigned long long* p) {
    asm volatile("red.release.gpu.global.add.u64 [%0], 1;" :: "l"(p) : "memory");
}
__device__ __forceinline__ unsigned long long ld_acquire(unsigned long long* p) {
    unsigned long long v;
    asm volatile("ld.acquire.gpu.global.u64 %0, [%1];" : "=l"(v) : "l"(p) : "memory");
    return v;
}

// ---------------- persistent scan kernel config ------------------------------
#define NBLK 128          // 1 block/SM, co-resident -> barrier safe
#define NTHR 256          // 8 warps
#define JT   16           // j's per block  (512 / 32 j-tiles)
#define BT   8            // batches per block (32 / 4 groups)
#define ROWS 48           // 3 gates * JT
#define GRPBLK 32         // blocks per barrier group (same batch-group)

// Barrier over the 32 blocks sharing one batch-group (CG grid.sync pattern:
// bar.sync -> owner release-add -> acquire-spin -> bar.sync). Monotonic
// counters keep graph replays correct. No membar.gpu, no L1 flush.
// Owner = last thread (warp 7) so it doesn't sit on the gate-math critical path.
__device__ __forceinline__ void group_barrier(int grp)
{
    __syncthreads();
    if (threadIdx.x == NTHR - 1) {
        unsigned long long old = atom_add_release(&g_cnt4[grp][0]);
        unsigned long long epoch = old >> 5;              // /GRPBLK
        if ((old & (GRPBLK - 1)) == GRPBLK - 1) {
            red_add_release(&g_gen4[grp][0]);             // release all
        } else {
            while (ld_acquire(&g_gen4[grp][0]) <= epoch) { }
        }
    }
    __syncthreads();
}

// One launch runs one full GRU layer scan (2048 steps).
// Wh tile lives in REGISTERS (packed f32x2), h slice staged to SMEM each step.
__global__ __launch_bounds__(NTHR, 1)
void gru_scan_kernel(const float* __restrict__ ip,   // [S][B][3H] (bi included)
                     const float* __restrict__ Wh,   // [3H][H]
                     const float* __restrict__ bh,   // [3H]
                     float* __restrict__ y,          // l0: [s][b][h]; l1: [b][s][h]
                     float* __restrict__ hout,       // last hidden (layer1 only)
                     int last_layer)
{
    __shared__ __align__(16) float h_s[BT * H];        // 16 KB
    __shared__ float hp_s[ROWS * BT];                  // 1.5 KB

    const int tid  = threadIdx.x;
    const int w    = tid >> 5;          // warp 0..7
    const int lane = tid & 31;
    const int bid  = blockIdx.x;
    const int jt   = bid >> 2;          // 0..31
    const int bt   = bid & 3;           // 0..3 (barrier group)
    const int j0   = jt * JT;
    const int b0   = bt * BT;

    // ---- load this warp's 6 Wh rows into packed registers (once) ------------
    // local row r_loc = w*6+rr; gate = r_loc/16; global row = gate*H + j0 + r_loc%16
    unsigned long long wreg[6][8];
    #pragma unroll
    for (int rr = 0; rr < 6; rr++) {
        int r_loc = w * 6 + rr;
        int grow  = (r_loc >> 4) * H + j0 + (r_loc & 15);
        const unsigned long long* src =
            (const unsigned long long*)(Wh + (size_t)grow * H);
        #pragma unroll
        for (int i = 0; i < 8; i++)
            wreg[rr][i] = __ldg(src + lane + 32 * i);
    }

    // ---- gate-phase constants (threads 0..127 own one (j,b) output each) ----
    float bhr = 0.f, bhz = 0.f, bhn = 0.f;
    int g_jl = 0, g_bb = 0, bglob = 0;
    const float* ipp = ip;
    const bool gthread = (tid < JT * BT);
    if (gthread) {
        g_jl  = tid >> 3;
        g_bb  = tid & 7;
        bglob = b0 + g_bb;
        int j = j0 + g_jl;
        bhr = __ldg(bh + j); bhz = __ldg(bh + H + j); bhn = __ldg(bh + 2 * H + j);
        ipp = ip + (size_t)bglob * G3 + (j0 + g_jl);
    }

    // prefetch ip for t=0
    float ipr = 0.f, ipz = 0.f, ipn = 0.f;
    if (gthread) {
        ipr = __ldg(ipp);
        ipz = __ldg(ipp + H);
        ipn = __ldg(ipp + 2 * H);
    }

    const unsigned long long* h2 = (const unsigned long long*)h_s;

    for (int t = 0; t < Sz; t++) {
        // ---- stage current hidden slice (8 batches x 512) into smem ---------
        {
            const float4* hsrc = (const float4*)(&g_h[t & 1][b0 * H]);
            float4* hdst = (float4*)h_s;
            #pragma unroll
            for (int i = 0; i < (BT * H / 4) / NTHR; i++) {    // 4 iters
                int idx = tid + i * NTHR;
                float4 v;
                if (t == 0) v = make_float4(0.f, 0.f, 0.f, 0.f);
                else        v = __ldcg(hsrc + idx);            // bypass stale L1
                hdst[idx] = v;
            }
        }
        __syncthreads();

        // ---- hp = Wh_tile @ h : warp = 6 rows x 8 batches, lanes split k ----
        unsigned long long acc[6][8];
        #pragma unroll
        for (int rr = 0; rr < 6; rr++)
            #pragma unroll
            for (int b = 0; b < 8; b++) acc[rr][b] = 0ULL;

        #pragma unroll
        for (int i = 0; i < 8; i++) {                          // packed-k chunks
            int p = lane + 32 * i;                             // k pair index
            unsigned long long hv[8];
            #pragma unroll
            for (int b = 0; b < 8; b++) hv[b] = h2[b * (H / 2) + p];
            #pragma unroll
            for (int rr = 0; rr < 6; rr++)
                #pragma unroll
                for (int b = 0; b < 8; b++)
                    FMA2(acc[rr][b], wreg[rr][i], hv[b], acc[rr][b]);
        }

        #pragma unroll
        for (int rr = 0; rr < 6; rr++)
            #pragma unroll
            for (int b = 0; b < 8; b++) {
                float2 f = unpack2(acc[rr][b]);
                float v = f.x + f.y;
                v += __shfl_xor_sync(0xffffffffu, v, 16);
                v += __shfl_xor_sync(0xffffffffu, v, 8);
                v += __shfl_xor_sync(0xffffffffu, v, 4);
                v += __shfl_xor_sync(0xffffffffu, v, 2);
                v += __shfl_xor_sync(0xffffffffu, v, 1);
                if (lane == 0) hp_s[(w * 6 + rr) * BT + b] = v;
            }
        __syncthreads();

        // ---- gates + state update ------------------------------------------
        if (gthread) {
            float hpr = hp_s[g_jl * BT + g_bb] + bhr;
            float hpz = hp_s[(JT + g_jl) * BT + g_bb] + bhz;
            float hpn = hp_s[(2 * JT + g_jl) * BT + g_bb] + bhn;
            float hprev = h_s[g_bb * H + (j0 + g_jl)];
            float r = 1.f / (1.f + __expf(-(ipr + hpr)));
            float z = 1.f / (1.f + __expf(-(ipz + hpz)));
            float n = tanhf(ipn + r * hpn);
            float hy = (1.f - z) * n + z * hprev;
            int j = j0 + g_jl;
            __stcg(&g_h[(t + 1) & 1][bglob * H + j], hy);
            if (last_layer) {
                y[((size_t)bglob * Sz + t) * H + j] = hy;
                if (t == Sz - 1) hout[bglob * H + j] = hy;
            } else {
                y[((size_t)t * Bz + bglob) * H + j] = hy;
            }
            // prefetch next step's ip (DRAM latency hides under the barrier)
            if (t != Sz - 1) {
                const float* p = ipp + (size_t)(t + 1) * (Bz * G3);
                ipr = __ldg(p);
                ipz = __ldg(p + H);
                ipn = __ldg(p + 2 * H);
            }
        }
        if (t != Sz - 1) group_barrier(bt);
    }
}

// ---------------- fp32 input-projection GEMM (f32x2 + double-buffered) -------
// C[m][g] = sum_d A[row(m)][d] * W[g][d] + bias[g];  M=65536, N=1536, K=512
// row(m) offset = (m&31)*strideB + (m>>5)*strideS
#define GBM 128
#define GBN 128
#define GBK 8

__global__ __launch_bounds__(256, 1)
void gemm_wi_kernel(const float* __restrict__ A, const float* __restrict__ W,
                    const float* __restrict__ bias, float* __restrict__ C,
                    int strideB, int strideS)
{
    __shared__ __align__(16) float As[2][GBK][GBM];
    __shared__ __align__(16) float Bs[2][GBK][GBN];

    const int tid = threadIdx.x;
    const int m0 = blockIdx.y * GBM;
    const int n0 = blockIdx.x * GBN;
    const int ty = tid >> 4, tx = tid & 15;

    const int lrow = tid >> 1;            // 0..127
    const int lk   = (tid & 1) * 4;       // 0 or 4

    const int am = m0 + lrow;
    const size_t aoff = (size_t)(am & 31) * strideB + (size_t)(am >> 5) * strideS;
    const size_t boff = (size_t)(n0 + lrow) * H;

    unsigned long long acc2[8][4];        // 8 m-rows x 4 packed n-pairs
    #pragma unroll
    for (int i = 0; i < 8; i++)
        #pragma unroll
        for (int j = 0; j < 4; j++) acc2[i][j] = 0ULL;

    // prologue: load k-tile 0 into buffer 0
    {
        float4 av = *(const float4*)(A + aoff + lk);
        float4 bv = *(const float4*)(W + boff + lk);
        As[0][lk + 0][lrow] = av.x; As[0][lk + 1][lrow] = av.y;
        As[0][lk + 2][lrow] = av.z; As[0][lk + 3][lrow] = av.w;
        Bs[0][lk + 0][lrow] = bv.x; Bs[0][lk + 1][lrow] = bv.y;
        Bs[0][lk + 2][lrow] = bv.z; Bs[0][lk + 3][lrow] = bv.w;
    }
    __syncthreads();

    int buf = 0;
    for (int k0 = 0; k0 < H; k0 += GBK) {
        // issue next tile's global loads early (latency hides under compute)
        float4 av, bv;
        const bool more = (k0 + GBK < H);
        if (more) {
            av = *(const float4*)(A + aoff + k0 + GBK + lk);
            bv = *(const float4*)(W + boff + k0 + GBK + lk);
        }

        #pragma unroll
        for (int k = 0; k < GBK; k++) {
            float4 a0 = *(float4*)&As[buf][k][ty * 8];
            float4 a1 = *(float4*)&As[buf][k][ty * 8 + 4];
            float4 b0 = *(float4*)&Bs[buf][k][tx * 8];
            float4 b1 = *(float4*)&Bs[buf][k][tx * 8 + 4];
            unsigned long long a2[8];
            a2[0] = pack2(a0.x, a0.x); a2[1] = pack2(a0.y, a0.y);
            a2[2] = pack2(a0.z, a0.z); a2[3] = pack2(a0.w, a0.w);
            a2[4] = pack2(a1.x, a1.x); a2[5] = pack2(a1.y, a1.y);
            a2[6] = pack2(a1.z, a1.z); a2[7] = pack2(a1.w, a1.w);
            unsigned long long b2[4];
            b2[0] = pack2(b0.x, b0.y); b2[1] = pack2(b0.z, b0.w);
            b2[2] = pack2(b1.x, b1.y); b2[3] = pack2(b1.z, b1.w);
            #pragma unroll
            for (int i = 0; i < 8; i++)
                #pragma unroll
                for (int j = 0; j < 4; j++)
                    FMA2(acc2[i][j], a2[i], b2[j], acc2[i][j]);
        }

        if (more) {
            int nb = buf ^ 1;
            As[nb][lk + 0][lrow] = av.x; As[nb][lk + 1][lrow] = av.y;
            As[nb][lk + 2][lrow] = av.z; As[nb][lk + 3][lrow] = av.w;
            Bs[nb][lk + 0][lrow] = bv.x; Bs[nb][lk + 1][lrow] = bv.y;
            Bs[nb][lk + 2][lrow] = bv.z; Bs[nb][lk + 3][lrow] = bv.w;
            __syncthreads();
            buf = nb;
        }
    }

    float bia[8];
    #pragma unroll
    for (int j = 0; j < 8; j++) bia[j] = __ldg(bias + n0 + tx * 8 + j);

    #pragma unroll
    for (int i = 0; i < 8; i++) {
        int m = m0 + ty * 8 + i;
        float* crow = C + (size_t)m * G3 + n0 + tx * 8;
        float2 p0 = unpack2(acc2[i][0]);
        float2 p1 = unpack2(acc2[i][1]);
        float2 p2 = unpack2(acc2[i][2]);
        float2 p3 = unpack2(acc2[i][3]);
        float4 o0 = make_float4(p0.x + bia[0], p0.y + bia[1],
                                p1.x + bia[2], p1.y + bia[3]);
        float4 o1 = make_float4(p2.x + bia[4], p2.y + bia[5],
                                p3.x + bia[6], p3.y + bia[7]);
        *(float4*)(crow)     = o0;
        *(float4*)(crow + 4) = o1;
    }
}

// ---------------- launch ------------------------------------------------------
extern "C" void kernel_launch(void* const* d_in, const int* in_sizes, int n_in,
                              void* d_out, int out_size)
{
    const float* x   = (const float*)d_in[0];
    const float* Wi0 = (const float*)d_in[1];
    const float* bi0 = (const float*)d_in[2];
    const float* Wh0 = (const float*)d_in[3];
    const float* bh0 = (const float*)d_in[4];
    const float* Wi1 = (const float*)d_in[5];
    const float* bi1 = (const float*)d_in[6];
    const float* Wh1 = (const float*)d_in[7];
    const float* bh1 = (const float*)d_in[8];
    float* out = (float*)d_out;

    float *ip, *y0;
    cudaGetSymbolAddress((void**)&ip, g_ip);
    cudaGetSymbolAddress((void**)&y0, g_y0);

    dim3 gg(G3 / GBN, (Bz * Sz) / GBM);   // 12 x 512

    // layer 0: ip = x @ Wi0^T + bi0, then scan
    gemm_wi_kernel<<<gg, 256>>>(x, Wi0, bi0, ip, Sz * H, H);
    gru_scan_kernel<<<NBLK, NTHR>>>(ip, Wh0, bh0, y0, nullptr, 0);

    // layer 1: ip = y0 @ Wi1^T + bi1 (y0 is [s][b][h] -> rows contiguous), then scan
    gemm_wi_kernel<<<gg, 256>>>(y0, Wi1, bi1, ip, H, Bz * H);
    gru_scan_kernel<<<NBLK, NTHR>>>(ip, Wh1, bh1, out,
                                    out + (size_t)Bz * Sz * H, 1);

    (void)in_sizes; (void)n_in; (void)out_size;
}